// round 1
// baseline (speedup 1.0000x reference)
#include <cuda_runtime.h>

// ---------------------------------------------------------------------------
// QuantumRNNCell: 6-qubit statevector sim (warp-per-element) + fused linear
// out[b,h] = hx[b,h] + sum_j q[b,j] * fc_w[h,j] + fc_b[h]
// Inputs (metadata order): x (B,6) f32 | hx (B,1024) f32 | q_weights (3,6) f32
//                          | fc_w (1024,6) f32 | fc_b (1024,) f32
// Output: (B,1024) f32
// ---------------------------------------------------------------------------

#define NQ 6
#define NLAYERS 3
#define HDIM 1024
#define MAXB 32768

// scratch for the per-element PauliZ expvals (B,6)
__device__ float g_qexp[MAXB * NQ];

// ---- gate helpers -----------------------------------------------------------
// Lane L holds amplitudes for basis states s = L (a0) and s = L + 32 (a1).
// Wire w corresponds to state bit (5 - w); wire 0 = MSB = the a0/a1 split.
// a[4] = { re0, im0, re1, im1 }

__device__ __forceinline__ void apply_rx(int w, float a[4], float c, float s,
                                         unsigned lane) {
    if (w == 0) {
        float nr0 = c * a[0] + s * a[3];
        float ni0 = c * a[1] - s * a[2];
        float nr1 = c * a[2] + s * a[1];
        float ni1 = c * a[3] - s * a[0];
        a[0] = nr0; a[1] = ni0; a[2] = nr1; a[3] = ni1;
    } else {
        int m = 1 << (5 - w);
        float or0 = __shfl_xor_sync(0xFFFFFFFFu, a[0], m);
        float oi0 = __shfl_xor_sync(0xFFFFFFFFu, a[1], m);
        float or1 = __shfl_xor_sync(0xFFFFFFFFu, a[2], m);
        float oi1 = __shfl_xor_sync(0xFFFFFFFFu, a[3], m);
        // symmetric: new = c*self - i*s*other  (both bit values)
        a[0] = c * a[0] + s * oi0;
        a[1] = c * a[1] - s * or0;
        a[2] = c * a[2] + s * oi1;
        a[3] = c * a[3] - s * or1;
    }
}

__device__ __forceinline__ void apply_ry(int w, float a[4], float c, float s,
                                         unsigned lane) {
    if (w == 0) {
        float nr0 = c * a[0] - s * a[2];
        float ni0 = c * a[1] - s * a[3];
        float nr1 = s * a[0] + c * a[2];
        float ni1 = s * a[1] + c * a[3];
        a[0] = nr0; a[1] = ni0; a[2] = nr1; a[3] = ni1;
    } else {
        int m = 1 << (5 - w);
        float sg = (lane & (unsigned)m) ? s : -s;  // bit=0: -s*other ; bit=1: +s*other
        float or0 = __shfl_xor_sync(0xFFFFFFFFu, a[0], m);
        float oi0 = __shfl_xor_sync(0xFFFFFFFFu, a[1], m);
        float or1 = __shfl_xor_sync(0xFFFFFFFFu, a[2], m);
        float oi1 = __shfl_xor_sync(0xFFFFFFFFu, a[3], m);
        a[0] = c * a[0] + sg * or0;
        a[1] = c * a[1] + sg * oi0;
        a[2] = c * a[2] + sg * or1;
        a[3] = c * a[3] + sg * oi1;
    }
}

__device__ __forceinline__ void apply_rz(int w, float a[4], float c, float s,
                                         unsigned lane) {
    // diagonal: amp *= (c + i*sx) where sx = -s if wire-bit==0 else +s
    float s0, s1;
    if (w == 0) {
        s0 = -s; s1 = s;
    } else {
        float sg = (lane & (unsigned)(1 << (5 - w))) ? s : -s;
        s0 = sg; s1 = sg;
    }
    float nr0 = c * a[0] - s0 * a[1];
    float ni0 = c * a[1] + s0 * a[0];
    float nr1 = c * a[2] - s1 * a[3];
    float ni1 = c * a[3] + s1 * a[2];
    a[0] = nr0; a[1] = ni0; a[2] = nr1; a[3] = ni1;
}

// CNOT with control q, target (q+1)%6
__device__ __forceinline__ void apply_cnot_ring(int q, float a[4], unsigned lane) {
    if (q == 0) {
        // control = bit5 (the a1 half), target bit4 -> lane-xor 16 on a1 only
        a[2] = __shfl_xor_sync(0xFFFFFFFFu, a[2], 16);
        a[3] = __shfl_xor_sync(0xFFFFFFFFu, a[3], 16);
    } else if (q == 5) {
        // control = bit0 of lane, target = bit5 -> swap a0<->a1 where lane&1
        if (lane & 1u) {
            float t;
            t = a[0]; a[0] = a[2]; a[2] = t;
            t = a[1]; a[1] = a[3]; a[3] = t;
        }
    } else {
        int cb = 5 - q;          // control bit of lane
        int tm = 1 << (4 - q);   // target lane-xor mask
        bool ctrl = (lane & (unsigned)(1 << cb)) != 0;
        float v0 = __shfl_xor_sync(0xFFFFFFFFu, a[0], tm);
        float v1 = __shfl_xor_sync(0xFFFFFFFFu, a[1], tm);
        float v2 = __shfl_xor_sync(0xFFFFFFFFu, a[2], tm);
        float v3 = __shfl_xor_sync(0xFFFFFFFFu, a[3], tm);
        if (ctrl) { a[0] = v0; a[1] = v1; a[2] = v2; a[3] = v3; }
    }
}

// ---- kernel 1: one warp per batch element ----------------------------------
__global__ __launch_bounds__(256, 8)
void qsim_kernel(const float* __restrict__ x,
                 const float* __restrict__ qw,  // (3,6)
                 int B) {
    int gwarp = (blockIdx.x * blockDim.x + threadIdx.x) >> 5;
    unsigned lane = threadIdx.x & 31u;
    if (gwarp >= B) return;
    const int b = gwarp;

    // precompute half-angle sin/cos of the 6 input angles (uniform loads)
    float xc[NQ], xs[NQ];
#pragma unroll
    for (int j = 0; j < NQ; j++) {
        float th = __ldg(&x[b * NQ + j]) * 0.5f;
        sincosf(th, &xs[j], &xc[j]);
    }

    // |0...0>
    float a[4];
    a[0] = (lane == 0) ? 1.0f : 0.0f;
    a[1] = 0.0f; a[2] = 0.0f; a[3] = 0.0f;

    // encoding: RX(x[i]) RY(x[i+1]) RZ(x[i+2]) on wire i
#pragma unroll
    for (int i = 0; i < NQ; i++) {
        int j1 = (i + 1) % NQ, j2 = (i + 2) % NQ;
        apply_rx(i, a, xc[i], xs[i], lane);
        apply_ry(i, a, xc[j1], xs[j1], lane);
        apply_rz(i, a, xc[j2], xs[j2], lane);
    }

    // variational layers
#pragma unroll
    for (int l = 0; l < NLAYERS; l++) {
#pragma unroll
        for (int q = 0; q < NQ; q++) {
            float th = __ldg(&qw[l * NQ + q]) * 0.5f;
            float s, c;
            sincosf(th, &s, &c);
            apply_ry(q, a, c, s, lane);
        }
#pragma unroll
        for (int q = 0; q < NQ; q++) apply_cnot_ring(q, a, lane);
    }

    // PauliZ expvals
    float p0 = a[0] * a[0] + a[1] * a[1];
    float p1 = a[2] * a[2] + a[3] * a[3];
    float e[NQ];
    e[0] = p0 - p1;  // wire 0 sign = bit5
#pragma unroll
    for (int j = 1; j < NQ; j++) {
        float sg = (lane & (unsigned)(1 << (5 - j))) ? -1.0f : 1.0f;
        e[j] = sg * (p0 + p1);
    }
#pragma unroll
    for (int off = 16; off; off >>= 1) {
#pragma unroll
        for (int j = 0; j < NQ; j++)
            e[j] += __shfl_xor_sync(0xFFFFFFFFu, e[j], off);
    }
    if (lane == 0) {
#pragma unroll
        for (int j = 0; j < NQ; j++) g_qexp[b * NQ + j] = e[j];
    }
}

// ---- kernel 2: streaming residual + tiny GEMV ------------------------------
__global__ __launch_bounds__(256, 4)
void out_kernel(const float* __restrict__ hx,
                const float* __restrict__ fc_w,   // (1024, 6)
                const float* __restrict__ fc_b,   // (1024,)
                float* __restrict__ out,
                int B, int rowsPerBlock) {
    __shared__ float4 sw[NQ][HDIM / 4];
    __shared__ float4 sb[HDIM / 4];

    int tid = threadIdx.x;      // 256 threads, each owns cols 4*tid .. 4*tid+3
    {
        int h0 = 4 * tid;
#pragma unroll
        for (int j = 0; j < NQ; j++) {
            sw[j][tid] = make_float4(fc_w[(h0 + 0) * NQ + j],
                                     fc_w[(h0 + 1) * NQ + j],
                                     fc_w[(h0 + 2) * NQ + j],
                                     fc_w[(h0 + 3) * NQ + j]);
        }
        sb[tid] = make_float4(fc_b[h0], fc_b[h0 + 1], fc_b[h0 + 2], fc_b[h0 + 3]);
    }
    __syncthreads();

    int r0 = blockIdx.x * rowsPerBlock;
    int r1 = min(r0 + rowsPerBlock, B);
    for (int b = r0; b < r1; b++) {
        float q0 = g_qexp[b * NQ + 0];
        float q1 = g_qexp[b * NQ + 1];
        float q2 = g_qexp[b * NQ + 2];
        float q3 = g_qexp[b * NQ + 3];
        float q4 = g_qexp[b * NQ + 4];
        float q5 = g_qexp[b * NQ + 5];

        const float4* hr = (const float4*)(hx + (size_t)b * HDIM);
        float4* orow = (float4*)(out + (size_t)b * HDIM);

        float4 v = hr[tid];
        float4 acc = sb[tid];
        float4 w;
        w = sw[0][tid]; acc.x += q0 * w.x; acc.y += q0 * w.y; acc.z += q0 * w.z; acc.w += q0 * w.w;
        w = sw[1][tid]; acc.x += q1 * w.x; acc.y += q1 * w.y; acc.z += q1 * w.z; acc.w += q1 * w.w;
        w = sw[2][tid]; acc.x += q2 * w.x; acc.y += q2 * w.y; acc.z += q2 * w.z; acc.w += q2 * w.w;
        w = sw[3][tid]; acc.x += q3 * w.x; acc.y += q3 * w.y; acc.z += q3 * w.z; acc.w += q3 * w.w;
        w = sw[4][tid]; acc.x += q4 * w.x; acc.y += q4 * w.y; acc.z += q4 * w.z; acc.w += q4 * w.w;
        w = sw[5][tid]; acc.x += q5 * w.x; acc.y += q5 * w.y; acc.z += q5 * w.z; acc.w += q5 * w.w;

        v.x += acc.x; v.y += acc.y; v.z += acc.z; v.w += acc.w;
        orow[tid] = v;
    }
}

// ---- launch ----------------------------------------------------------------
extern "C" void kernel_launch(void* const* d_in, const int* in_sizes, int n_in,
                              void* d_out, int out_size) {
    const float* x    = (const float*)d_in[0];   // (B,6)
    const float* hx   = (const float*)d_in[1];   // (B,1024)
    const float* qw   = (const float*)d_in[2];   // (3,6)
    const float* fc_w = (const float*)d_in[3];   // (1024,6)
    const float* fc_b = (const float*)d_in[4];   // (1024,)
    float* out = (float*)d_out;

    int B = in_sizes[0] / NQ;
    if (B > MAXB) B = MAXB;

    // kernel 1: one warp per element, 8 warps per block
    {
        int warpsPerBlock = 8;
        int blocks = (B + warpsPerBlock - 1) / warpsPerBlock;
        qsim_kernel<<<blocks, warpsPerBlock * 32>>>(x, qw, B);
    }
    // kernel 2: streaming output
    {
        int rowsPerBlock = 16;
        int blocks = (B + rowsPerBlock - 1) / rowsPerBlock;
        out_kernel<<<blocks, 256>>>(hx, fc_w, fc_b, out, B, rowsPerBlock);
    }
}

// round 2
// speedup vs baseline: 1.3413x; 1.3413x over previous
#include <cuda_runtime.h>

// ---------------------------------------------------------------------------
// QuantumRNNCell fused: 6-qubit statevector sim (warp-per-row) + streaming
// out[b,h] = hx[b,h] + sum_j q[b,j] * fc_w[h,j] + fc_b[h]
// Inputs: x (B,6) f32 | hx (B,1024) f32 | q_weights (3,6) f32
//         | fc_w (1024,6) f32 | fc_b (1024,) f32      Output: (B,1024) f32
// ---------------------------------------------------------------------------

#define NQ 6
#define NLAYERS 3
#define HDIM 1024
#define ROWS 32   // rows per block

// ---- gate helpers -----------------------------------------------------------
// Lane L holds amplitudes for basis states s = L (a0) and s = L + 32 (a1).
// Wire w corresponds to state bit (5 - w); wire 0 = MSB = the a0/a1 split.
// a[4] = { re0, im0, re1, im1 }

__device__ __forceinline__ void apply_rx(int w, float a[4], float c, float s,
                                         unsigned lane) {
    if (w == 0) {
        float nr0 = c * a[0] + s * a[3];
        float ni0 = c * a[1] - s * a[2];
        float nr1 = c * a[2] + s * a[1];
        float ni1 = c * a[3] - s * a[0];
        a[0] = nr0; a[1] = ni0; a[2] = nr1; a[3] = ni1;
    } else {
        int m = 1 << (5 - w);
        float or0 = __shfl_xor_sync(0xFFFFFFFFu, a[0], m);
        float oi0 = __shfl_xor_sync(0xFFFFFFFFu, a[1], m);
        float or1 = __shfl_xor_sync(0xFFFFFFFFu, a[2], m);
        float oi1 = __shfl_xor_sync(0xFFFFFFFFu, a[3], m);
        a[0] = c * a[0] + s * oi0;
        a[1] = c * a[1] - s * or0;
        a[2] = c * a[2] + s * oi1;
        a[3] = c * a[3] - s * or1;
    }
}

__device__ __forceinline__ void apply_ry(int w, float a[4], float c, float s,
                                         unsigned lane) {
    if (w == 0) {
        float nr0 = c * a[0] - s * a[2];
        float ni0 = c * a[1] - s * a[3];
        float nr1 = s * a[0] + c * a[2];
        float ni1 = s * a[1] + c * a[3];
        a[0] = nr0; a[1] = ni0; a[2] = nr1; a[3] = ni1;
    } else {
        int m = 1 << (5 - w);
        float sg = (lane & (unsigned)m) ? s : -s;
        float or0 = __shfl_xor_sync(0xFFFFFFFFu, a[0], m);
        float oi0 = __shfl_xor_sync(0xFFFFFFFFu, a[1], m);
        float or1 = __shfl_xor_sync(0xFFFFFFFFu, a[2], m);
        float oi1 = __shfl_xor_sync(0xFFFFFFFFu, a[3], m);
        a[0] = c * a[0] + sg * or0;
        a[1] = c * a[1] + sg * oi0;
        a[2] = c * a[2] + sg * or1;
        a[3] = c * a[3] + sg * oi1;
    }
}

__device__ __forceinline__ void apply_rz(int w, float a[4], float c, float s,
                                         unsigned lane) {
    float s0, s1;
    if (w == 0) {
        s0 = -s; s1 = s;
    } else {
        float sg = (lane & (unsigned)(1 << (5 - w))) ? s : -s;
        s0 = sg; s1 = sg;
    }
    float nr0 = c * a[0] - s0 * a[1];
    float ni0 = c * a[1] + s0 * a[0];
    float nr1 = c * a[2] - s1 * a[3];
    float ni1 = c * a[3] + s1 * a[2];
    a[0] = nr0; a[1] = ni0; a[2] = nr1; a[3] = ni1;
}

__device__ __forceinline__ void apply_cnot_ring(int q, float a[4], unsigned lane) {
    if (q == 0) {
        a[2] = __shfl_xor_sync(0xFFFFFFFFu, a[2], 16);
        a[3] = __shfl_xor_sync(0xFFFFFFFFu, a[3], 16);
    } else if (q == 5) {
        if (lane & 1u) {
            float t;
            t = a[0]; a[0] = a[2]; a[2] = t;
            t = a[1]; a[1] = a[3]; a[3] = t;
        }
    } else {
        int cb = 5 - q;
        int tm = 1 << (4 - q);
        bool ctrl = (lane & (unsigned)(1 << cb)) != 0;
        float v0 = __shfl_xor_sync(0xFFFFFFFFu, a[0], tm);
        float v1 = __shfl_xor_sync(0xFFFFFFFFu, a[1], tm);
        float v2 = __shfl_xor_sync(0xFFFFFFFFu, a[2], tm);
        float v3 = __shfl_xor_sync(0xFFFFFFFFu, a[3], tm);
        if (ctrl) { a[0] = v0; a[1] = v1; a[2] = v2; a[3] = v3; }
    }
}

// ---- fused kernel -----------------------------------------------------------
__global__ __launch_bounds__(256)
void fused_kernel(const float* __restrict__ x,
                  const float* __restrict__ hx,
                  const float* __restrict__ qw,    // (3,6)
                  const float* __restrict__ fc_w,  // (1024,6)
                  const float* __restrict__ fc_b,  // (1024,)
                  float* __restrict__ out,
                  int B) {
    __shared__ float4 sw[NQ][HDIM / 4];
    __shared__ float4 sb[HDIM / 4];
    __shared__ float  sq[ROWS][NQ];

    const int tid = threadIdx.x;          // 256 threads
    const int warp = tid >> 5;
    const unsigned lane = tid & 31u;
    const int row0 = blockIdx.x * ROWS;

    // ---- load fc weights into smem (transposed to column-broadcast form) ----
    {
        int h0 = 4 * tid;
#pragma unroll
        for (int j = 0; j < NQ; j++) {
            sw[j][tid] = make_float4(fc_w[(h0 + 0) * NQ + j],
                                     fc_w[(h0 + 1) * NQ + j],
                                     fc_w[(h0 + 2) * NQ + j],
                                     fc_w[(h0 + 3) * NQ + j]);
        }
        sb[tid] = make_float4(fc_b[h0], fc_b[h0 + 1], fc_b[h0 + 2], fc_b[h0 + 3]);
    }

    // ---- precompute half-angle sin/cos of variational weights (uniform) ----
    float qwc[NLAYERS * NQ], qws[NLAYERS * NQ];
#pragma unroll
    for (int i = 0; i < NLAYERS * NQ; i++) {
        __sincosf(__ldg(&qw[i]) * 0.5f, &qws[i], &qwc[i]);
    }

    // ---- phase 1: each warp simulates 4 rows ----
#pragma unroll
    for (int k = 0; k < 4; k++) {
        int r = warp * 4 + k;
        int b = row0 + r;
        if (b < B) {
            float xc[NQ], xs[NQ];
#pragma unroll
            for (int j = 0; j < NQ; j++) {
                __sincosf(__ldg(&x[b * NQ + j]) * 0.5f, &xs[j], &xc[j]);
            }

            float a[4];
            a[0] = (lane == 0) ? 1.0f : 0.0f;
            a[1] = 0.0f; a[2] = 0.0f; a[3] = 0.0f;

#pragma unroll
            for (int i = 0; i < NQ; i++) {
                int j1 = (i + 1) % NQ, j2 = (i + 2) % NQ;
                apply_rx(i, a, xc[i], xs[i], lane);
                apply_ry(i, a, xc[j1], xs[j1], lane);
                apply_rz(i, a, xc[j2], xs[j2], lane);
            }

#pragma unroll
            for (int l = 0; l < NLAYERS; l++) {
#pragma unroll
                for (int q = 0; q < NQ; q++)
                    apply_ry(q, a, qwc[l * NQ + q], qws[l * NQ + q], lane);
#pragma unroll
                for (int q = 0; q < NQ; q++) apply_cnot_ring(q, a, lane);
            }

            float p0 = a[0] * a[0] + a[1] * a[1];
            float p1 = a[2] * a[2] + a[3] * a[3];
            float e[NQ];
            e[0] = p0 - p1;
#pragma unroll
            for (int j = 1; j < NQ; j++) {
                float sg = (lane & (unsigned)(1 << (5 - j))) ? -1.0f : 1.0f;
                e[j] = sg * (p0 + p1);
            }
#pragma unroll
            for (int off = 16; off; off >>= 1) {
#pragma unroll
                for (int j = 0; j < NQ; j++)
                    e[j] += __shfl_xor_sync(0xFFFFFFFFu, e[j], off);
            }
            if (lane == 0) {
#pragma unroll
                for (int j = 0; j < NQ; j++) sq[r][j] = e[j];
            }
        }
    }
    __syncthreads();

    // ---- phase 2: stream 32 rows of hx -> out with tiny GEMV ----
#pragma unroll 4
    for (int r = 0; r < ROWS; r++) {
        int b = row0 + r;
        if (b >= B) break;
        float q0 = sq[r][0], q1 = sq[r][1], q2 = sq[r][2];
        float q3 = sq[r][3], q4 = sq[r][4], q5 = sq[r][5];

        const float4* hr = (const float4*)(hx + (size_t)b * HDIM);
        float4* orow = (float4*)(out + (size_t)b * HDIM);

        float4 v = hr[tid];
        float4 acc = sb[tid];
        float4 w;
        w = sw[0][tid]; acc.x += q0 * w.x; acc.y += q0 * w.y; acc.z += q0 * w.z; acc.w += q0 * w.w;
        w = sw[1][tid]; acc.x += q1 * w.x; acc.y += q1 * w.y; acc.z += q1 * w.z; acc.w += q1 * w.w;
        w = sw[2][tid]; acc.x += q2 * w.x; acc.y += q2 * w.y; acc.z += q2 * w.z; acc.w += q2 * w.w;
        w = sw[3][tid]; acc.x += q3 * w.x; acc.y += q3 * w.y; acc.z += q3 * w.z; acc.w += q3 * w.w;
        w = sw[4][tid]; acc.x += q4 * w.x; acc.y += q4 * w.y; acc.z += q4 * w.z; acc.w += q4 * w.w;
        w = sw[5][tid]; acc.x += q5 * w.x; acc.y += q5 * w.y; acc.z += q5 * w.z; acc.w += q5 * w.w;

        v.x += acc.x; v.y += acc.y; v.z += acc.z; v.w += acc.w;
        orow[tid] = v;
    }
}

// ---- launch ----------------------------------------------------------------
extern "C" void kernel_launch(void* const* d_in, const int* in_sizes, int n_in,
                              void* d_out, int out_size) {
    const float* x    = (const float*)d_in[0];   // (B,6)
    const float* hx   = (const float*)d_in[1];   // (B,1024)
    const float* qw   = (const float*)d_in[2];   // (3,6)
    const float* fc_w = (const float*)d_in[3];   // (1024,6)
    const float* fc_b = (const float*)d_in[4];   // (1024,)
    float* out = (float*)d_out;

    int B = in_sizes[0] / NQ;

    int blocks = (B + ROWS - 1) / ROWS;
    fused_kernel<<<blocks, 256>>>(x, hx, qw, fc_w, fc_b, out, B);
}

// round 3
// speedup vs baseline: 1.9159x; 1.4283x over previous
#include <cuda_runtime.h>

// ---------------------------------------------------------------------------
// QuantumRNNCell fused persistent kernel:
//   out[b,h] = hx[b,h] + sum_j q[b,j] * fc_w[h,j] + fc_b[h]
// q[b,:] = PauliZ expvals of a 6-qubit circuit, simulated warp-per-row
// (64 amplitudes = 2 complex per lane, wire gates = lane shuffles).
// Pipeline: per 8-row tile, issue hx loads -> sim (hides load latency) ->
// barrier -> fused FMA + store. Persistent grid, double-buffered q smem.
// ---------------------------------------------------------------------------

#define NQ 6
#define NLAYERS 3
#define HDIM 1024
#define TR 8          // rows per tile == warps per block

// ---- gate helpers -----------------------------------------------------------
// Lane L holds amplitudes for basis states s = L (a0) and s = L + 32 (a1).
// Wire w corresponds to state bit (5 - w); wire 0 = MSB = the a0/a1 split.
// a[4] = { re0, im0, re1, im1 }

__device__ __forceinline__ void apply_rx(int w, float a[4], float c, float s,
                                         unsigned lane) {
    if (w == 0) {
        float nr0 = c * a[0] + s * a[3];
        float ni0 = c * a[1] - s * a[2];
        float nr1 = c * a[2] + s * a[1];
        float ni1 = c * a[3] - s * a[0];
        a[0] = nr0; a[1] = ni0; a[2] = nr1; a[3] = ni1;
    } else {
        int m = 1 << (5 - w);
        float or0 = __shfl_xor_sync(0xFFFFFFFFu, a[0], m);
        float oi0 = __shfl_xor_sync(0xFFFFFFFFu, a[1], m);
        float or1 = __shfl_xor_sync(0xFFFFFFFFu, a[2], m);
        float oi1 = __shfl_xor_sync(0xFFFFFFFFu, a[3], m);
        a[0] = c * a[0] + s * oi0;
        a[1] = c * a[1] - s * or0;
        a[2] = c * a[2] + s * oi1;
        a[3] = c * a[3] - s * or1;
    }
}

__device__ __forceinline__ void apply_ry(int w, float a[4], float c, float s,
                                         unsigned lane) {
    if (w == 0) {
        float nr0 = c * a[0] - s * a[2];
        float ni0 = c * a[1] - s * a[3];
        float nr1 = s * a[0] + c * a[2];
        float ni1 = s * a[1] + c * a[3];
        a[0] = nr0; a[1] = ni0; a[2] = nr1; a[3] = ni1;
    } else {
        int m = 1 << (5 - w);
        float sg = (lane & (unsigned)m) ? s : -s;
        float or0 = __shfl_xor_sync(0xFFFFFFFFu, a[0], m);
        float oi0 = __shfl_xor_sync(0xFFFFFFFFu, a[1], m);
        float or1 = __shfl_xor_sync(0xFFFFFFFFu, a[2], m);
        float oi1 = __shfl_xor_sync(0xFFFFFFFFu, a[3], m);
        a[0] = c * a[0] + sg * or0;
        a[1] = c * a[1] + sg * oi0;
        a[2] = c * a[2] + sg * or1;
        a[3] = c * a[3] + sg * oi1;
    }
}

__device__ __forceinline__ void apply_rz(int w, float a[4], float c, float s,
                                         unsigned lane) {
    float s0, s1;
    if (w == 0) {
        s0 = -s; s1 = s;
    } else {
        float sg = (lane & (unsigned)(1 << (5 - w))) ? s : -s;
        s0 = sg; s1 = sg;
    }
    float nr0 = c * a[0] - s0 * a[1];
    float ni0 = c * a[1] + s0 * a[0];
    float nr1 = c * a[2] - s1 * a[3];
    float ni1 = c * a[3] + s1 * a[2];
    a[0] = nr0; a[1] = ni0; a[2] = nr1; a[3] = ni1;
}

__device__ __forceinline__ void apply_cnot_ring(int q, float a[4], unsigned lane) {
    if (q == 0) {
        a[2] = __shfl_xor_sync(0xFFFFFFFFu, a[2], 16);
        a[3] = __shfl_xor_sync(0xFFFFFFFFu, a[3], 16);
    } else if (q == 5) {
        if (lane & 1u) {
            float t;
            t = a[0]; a[0] = a[2]; a[2] = t;
            t = a[1]; a[1] = a[3]; a[3] = t;
        }
    } else {
        int cb = 5 - q;
        int tm = 1 << (4 - q);
        bool ctrl = (lane & (unsigned)(1 << cb)) != 0;
        float v0 = __shfl_xor_sync(0xFFFFFFFFu, a[0], tm);
        float v1 = __shfl_xor_sync(0xFFFFFFFFu, a[1], tm);
        float v2 = __shfl_xor_sync(0xFFFFFFFFu, a[2], tm);
        float v3 = __shfl_xor_sync(0xFFFFFFFFu, a[3], tm);
        if (ctrl) { a[0] = v0; a[1] = v1; a[2] = v2; a[3] = v3; }
    }
}

// ---- fused persistent kernel ------------------------------------------------
__global__ __launch_bounds__(256, 3)
void fused_kernel(const float* __restrict__ x,
                  const float* __restrict__ hx,
                  const float* __restrict__ qw,    // (3,6)
                  const float* __restrict__ fc_w,  // (1024,6)
                  const float* __restrict__ fc_b,  // (1024,)
                  float* __restrict__ out,
                  int B, int ntiles) {
    __shared__ float4 sw[NQ][HDIM / 4];
    __shared__ float4 sb[HDIM / 4];
    __shared__ float  sq[2][TR][8];       // padded to 8 floats/row
    __shared__ float  swc[NLAYERS * NQ];  // layer-weight cos
    __shared__ float  sws[NLAYERS * NQ];  // layer-weight sin

    const int tid = threadIdx.x;          // 256 threads
    const int warp = tid >> 5;            // 0..7 == row within tile
    const unsigned lane = tid & 31u;

    // ---- one-time setup per persistent CTA ----
    {
        int h0 = 4 * tid;
#pragma unroll
        for (int j = 0; j < NQ; j++) {
            sw[j][tid] = make_float4(fc_w[(h0 + 0) * NQ + j],
                                     fc_w[(h0 + 1) * NQ + j],
                                     fc_w[(h0 + 2) * NQ + j],
                                     fc_w[(h0 + 3) * NQ + j]);
        }
        sb[tid] = make_float4(fc_b[h0], fc_b[h0 + 1], fc_b[h0 + 2], fc_b[h0 + 3]);
        if (tid < NLAYERS * NQ) {
            float s, c;
            __sincosf(__ldg(&qw[tid]) * 0.5f, &s, &c);
            swc[tid] = c; sws[tid] = s;
        }
    }
    __syncthreads();

    int buf = 0;
    for (int tile = blockIdx.x; tile < ntiles; tile += gridDim.x) {
        const int row0 = tile * TR;

        // ---- issue all hx loads for this tile up front (MLP = 8) ----
        float4 h[TR];
        const int nrows = min(TR, B - row0);
#pragma unroll
        for (int r = 0; r < TR; r++) {
            if (r < nrows)
                h[r] = ((const float4*)(hx + (size_t)(row0 + r) * HDIM))[tid];
        }

        // ---- sim: this warp handles row (row0 + warp); latency hides loads --
        const int b = row0 + warp;
        if (warp < nrows) {
            float xc[NQ], xs[NQ];
#pragma unroll
            for (int j = 0; j < NQ; j++) {
                __sincosf(__ldg(&x[b * NQ + j]) * 0.5f, &xs[j], &xc[j]);
            }

            float a[4];
            a[0] = (lane == 0) ? 1.0f : 0.0f;
            a[1] = 0.0f; a[2] = 0.0f; a[3] = 0.0f;

#pragma unroll
            for (int i = 0; i < NQ; i++) {
                int j1 = (i + 1) % NQ, j2 = (i + 2) % NQ;
                apply_rx(i, a, xc[i], xs[i], lane);
                apply_ry(i, a, xc[j1], xs[j1], lane);
                apply_rz(i, a, xc[j2], xs[j2], lane);
            }

#pragma unroll
            for (int l = 0; l < NLAYERS; l++) {
#pragma unroll
                for (int q = 0; q < NQ; q++)
                    apply_ry(q, a, swc[l * NQ + q], sws[l * NQ + q], lane);
#pragma unroll
                for (int q = 0; q < NQ; q++) apply_cnot_ring(q, a, lane);
            }

            float p0 = a[0] * a[0] + a[1] * a[1];
            float p1 = a[2] * a[2] + a[3] * a[3];
            float e[NQ];
            e[0] = p0 - p1;
#pragma unroll
            for (int j = 1; j < NQ; j++) {
                float sg = (lane & (unsigned)(1 << (5 - j))) ? -1.0f : 1.0f;
                e[j] = sg * (p0 + p1);
            }
#pragma unroll
            for (int off = 16; off; off >>= 1) {
#pragma unroll
                for (int j = 0; j < NQ; j++)
                    e[j] += __shfl_xor_sync(0xFFFFFFFFu, e[j], off);
            }
            if (lane == 0) {
#pragma unroll
                for (int j = 0; j < NQ; j++) sq[buf][warp][j] = e[j];
            }
        }
        __syncthreads();

        // ---- stream: fused residual + tiny GEMV, consume prefetched h[] ----
#pragma unroll
        for (int r = 0; r < TR; r++) {
            if (r >= nrows) break;
            float q0 = sq[buf][r][0], q1 = sq[buf][r][1], q2 = sq[buf][r][2];
            float q3 = sq[buf][r][3], q4 = sq[buf][r][4], q5 = sq[buf][r][5];

            float4 v = h[r];
            float4 acc = sb[tid];
            float4 w;
            w = sw[0][tid]; acc.x += q0 * w.x; acc.y += q0 * w.y; acc.z += q0 * w.z; acc.w += q0 * w.w;
            w = sw[1][tid]; acc.x += q1 * w.x; acc.y += q1 * w.y; acc.z += q1 * w.z; acc.w += q1 * w.w;
            w = sw[2][tid]; acc.x += q2 * w.x; acc.y += q2 * w.y; acc.z += q2 * w.z; acc.w += q2 * w.w;
            w = sw[3][tid]; acc.x += q3 * w.x; acc.y += q3 * w.y; acc.z += q3 * w.z; acc.w += q3 * w.w;
            w = sw[4][tid]; acc.x += q4 * w.x; acc.y += q4 * w.y; acc.z += q4 * w.z; acc.w += q4 * w.w;
            w = sw[5][tid]; acc.x += q5 * w.x; acc.y += q5 * w.y; acc.z += q5 * w.z; acc.w += q5 * w.w;

            v.x += acc.x; v.y += acc.y; v.z += acc.z; v.w += acc.w;
            ((float4*)(out + (size_t)(row0 + r) * HDIM))[tid] = v;
        }
        buf ^= 1;   // double buffer: next sim writes the other sq slot
    }
}

// ---- launch ----------------------------------------------------------------
extern "C" void kernel_launch(void* const* d_in, const int* in_sizes, int n_in,
                              void* d_out, int out_size) {
    const float* x    = (const float*)d_in[0];   // (B,6)
    const float* hx   = (const float*)d_in[1];   // (B,1024)
    const float* qw   = (const float*)d_in[2];   // (3,6)
    const float* fc_w = (const float*)d_in[3];   // (1024,6)
    const float* fc_b = (const float*)d_in[4];   // (1024,)
    float* out = (float*)d_out;

    int B = in_sizes[0] / NQ;
    int ntiles = (B + TR - 1) / TR;

    int grid = 148 * 3;                   // persistent: 3 CTAs per SM
    if (grid > ntiles) grid = ntiles;
    fused_kernel<<<grid, 256>>>(x, hx, qw, fc_w, fc_b, out, B, ntiles);
}